// round 16
// baseline (speedup 1.0000x reference)
#include <cuda_runtime.h>
#include <cuda_bf16.h>
#include <cstdint>
#include <math.h>

#define S_    1536
#define HID_  6144
#define NH_   64
#define DN_   128
#define DR_   64
#define DV_   128
#define QL_   1536
#define KVL_  512
#define DF_   576        // KVL + DR
#define QDIM_ 192        // DN + DR
#define KCAT_ 192        // DN + DR (scores K)

#define SM_SCALE_  0.07216878364870322f
#define SCALE_Q_   2.0f
#define SCALE_KV_  3.4641016151377544f

#define KC 32

typedef __nv_bfloat16 bf16;

// ---------------- scratch: activations/weights as (hi, lo) bf16 pairs -------
#define N_HID  ((size_t)S_ * HID_)
#define N_QLAT ((size_t)S_ * QL_)
#define N_Q    ((size_t)S_ * NH_ * QDIM_)
#define N_LAT  ((size_t)S_ * DF_)
#define N_KF   ((size_t)S_ * DF_)
#define N_KCAT ((size_t)NH_ * S_ * KCAT_)
#define N_VEFF ((size_t)NH_ * DV_ * S_)
#define N_SC   ((size_t)NH_ * S_ * S_)
#define N_AO   ((size_t)S_ * NH_ * DV_)
#define N_WQA  ((size_t)QL_ * HID_)
#define N_WQB  ((size_t)NH_ * QDIM_ * QL_)
#define N_WKVA ((size_t)DF_ * HID_)
#define N_WK   ((size_t)NH_ * DN_ * KVL_)
#define N_WV   ((size_t)NH_ * DV_ * KVL_)
#define N_WO   ((size_t)HID_ * NH_ * DV_)

__device__ __align__(256) unsigned short g_hid2 [2 * N_HID];
__device__ __align__(256) unsigned short g_qlat2[2 * N_QLAT];
__device__ __align__(256) unsigned short g_q2   [2 * N_Q];
__device__ __align__(256) unsigned short g_lat2 [2 * N_LAT];
__device__ __align__(256) unsigned short g_kf2  [2 * N_KF];
__device__ __align__(256) unsigned short g_kcat2[2 * N_KCAT];
__device__ __align__(256) unsigned short g_veff2[2 * N_VEFF];
__device__ __align__(256) unsigned short g_sc2  [2 * N_SC];
__device__ __align__(256) float          g_scf  [N_SC];
__device__ __align__(256) unsigned short g_ao2  [2 * N_AO];
__device__ __align__(256) unsigned short g_wqa2 [2 * N_WQA];
__device__ __align__(256) unsigned short g_wqb2 [2 * N_WQB];
__device__ __align__(256) unsigned short g_wkva2[2 * N_WKVA];
__device__ __align__(256) unsigned short g_wk2  [2 * N_WK];
__device__ __align__(256) unsigned short g_wv2  [2 * N_WV];
__device__ __align__(256) unsigned short g_wo2  [2 * N_WO];

// ---------------- helpers ----------------------------------------------------
__device__ __forceinline__ uint32_t smem_u32(const void* p) {
    uint32_t a;
    asm("{ .reg .u64 t; cvta.to.shared.u64 t, %1; cvt.u32.u64 %0, t; }" : "=r"(a) : "l"(p));
    return a;
}
#define CP_ASYNC16(dst, src, sz) \
    asm volatile("cp.async.cg.shared.global [%0], [%1], 16, %2;" :: "r"(dst), "l"(src), "r"(sz))
#define CP_COMMIT() asm volatile("cp.async.commit_group;" ::: "memory")
#define CP_WAIT(n)  asm volatile("cp.async.wait_group %0;" :: "n"(n) : "memory")

#define LDSM4(r0, r1, r2, r3, a) \
    asm volatile("ldmatrix.sync.aligned.m8n8.x4.shared.b16 {%0,%1,%2,%3}, [%4];" \
                 : "=r"(r0), "=r"(r1), "=r"(r2), "=r"(r3) : "r"(a))

__device__ __forceinline__ void mma_bf16(float* d, const unsigned* a, const unsigned* b) {
    asm volatile(
        "mma.sync.aligned.m16n8k16.row.col.f32.bf16.bf16.f32 "
        "{%0,%1,%2,%3}, {%4,%5,%6,%7}, {%8,%9}, {%0,%1,%2,%3};"
        : "+f"(d[0]), "+f"(d[1]), "+f"(d[2]), "+f"(d[3])
        : "r"(a[0]), "r"(a[1]), "r"(a[2]), "r"(a[3]), "r"(b[0]), "r"(b[1]));
}

__device__ __forceinline__ uint32_t off_swz(int row, int kc) {
    return (uint32_t)(row >> 1) * 128u +
           (uint32_t)(((((row & 1) << 2) + kc) ^ ((row >> 1) & 7)) * 16);
}

__device__ __forceinline__ float pget(const bf16* h, const bf16* l, long long i) {
    return __bfloat162float(h[i]) + __bfloat162float(l[i]);
}
__device__ __forceinline__ void pset(bf16* h, bf16* l, long long i, float v) {
    bf16 a = __float2bfloat16(v);
    h[i] = a;
    l[i] = __float2bfloat16(v - __bfloat162float(a));
}
__device__ __forceinline__ void unpack2(unsigned h, unsigned l, float& a, float& b) {
    a = __uint_as_float(h << 16) + __uint_as_float(l << 16);
    b = __uint_as_float(h & 0xffff0000u) + __uint_as_float(l & 0xffff0000u);
}
__device__ __forceinline__ void pack2(float a, float b, unsigned& h, unsigned& l) {
    bf16 ha = __float2bfloat16(a), hb = __float2bfloat16(b);
    bf16 la = __float2bfloat16(a - __bfloat162float(ha));
    bf16 lb = __float2bfloat16(b - __bfloat162float(hb));
    __nv_bfloat162 hv; hv.x = ha; hv.y = hb;
    __nv_bfloat162 lv; lv.x = la; lv.y = lb;
    h = *reinterpret_cast<unsigned*>(&hv);
    l = *reinterpret_cast<unsigned*>(&lv);
}

// flags: bit0 causal tile skip, bit1 K limited to row0+TM, bit2 fp32 C,
//        bit3 epilogue also copies roped k_pe into C cols [DN_, DN_+64)
template <int TM, int TN, int NSTAGE>
__global__ __launch_bounds__(256, 2) void mma_gemm(
    const bf16* __restrict__ Ahi, const bf16* __restrict__ Alo,
    const bf16* __restrict__ Bhi, const bf16* __restrict__ Blo,
    bf16* __restrict__ Chi, bf16* __restrict__ Clo, float* __restrict__ Cf,
    const bf16* __restrict__ KpeH, const bf16* __restrict__ KpeL,
    int M, int N, int K, int lda, int ldb, int ldc,
    long long sA, long long sB, long long sC, float alpha, int flags)
{
    constexpr uint32_t BUFA = (uint32_t)TM * 64u;
    constexpr uint32_t BUFB = (uint32_t)TN * 64u;
    constexpr uint32_t STB  = 2u * BUFA + 2u * BUFB;
    constexpr int NFR = TN / 32;
    constexpr int NLD = TN / 64;
    constexpr int NMI = TM / 32;

    const int row0 = blockIdx.y * TM;
    const int col0 = blockIdx.x * TN;
    if ((flags & 1) && col0 >= row0 + TM) return;

    const long long bz = blockIdx.z;
    Ahi += bz * sA;  Alo += bz * sA;
    Bhi += bz * sB;  Blo += bz * sB;
    if (flags & 4) Cf += bz * sC; else { Chi += bz * sC; Clo += bz * sC; }

    const int Keff = (flags & 2) ? min(K, row0 + TM) : K;
    const int KT = Keff / KC;

    extern __shared__ char smraw[];
    const uint32_t sbase = smem_u32(smraw);
    const int tid  = threadIdx.x;
    const int wid  = tid >> 5;
    const int lane = tid & 31;
    const int g    = lane >> 2;
    const int c    = lane & 3;
    const int m0   = (wid & 1) * (TM / 2);
    const int n0   = (wid >> 1) * (TN / 4);

    const int am_l = (lane & 7) + ((lane >> 3) & 1) * 8;
    const int ak_l = lane >> 4;
    const int bn_l = (lane & 7) + ((lane >> 4) & 1) * 8;
    const int bk_l = (lane >> 3) & 1;

    auto load_stage = [&](int kt) {
        const uint32_t base = sbase + (uint32_t)(kt % NSTAGE) * STB;
        const bf16* AgH = Ahi + (long long)row0 * lda + (long long)kt * KC;
        const bf16* AgL = Alo + (long long)row0 * lda + (long long)kt * KC;
        const bf16* BgH = Bhi + (long long)kt * KC;
        const bf16* BgL = Blo + (long long)kt * KC;
#pragma unroll
        for (int i = tid; i < TM * 4; i += 256) {     // A chunks (generic TM)
            const int m  = i >> 2;
            const int kc = i & 3;
            const uint32_t so = off_swz(m, kc);
            CP_ASYNC16(base + so,        AgH + (long long)m * lda + kc * 8, 16);
            CP_ASYNC16(base + BUFA + so, AgL + (long long)m * lda + kc * 8, 16);
        }
#pragma unroll
        for (int i = tid; i < TN * 4; i += 256) {     // B chunks
            const int m  = i >> 2;
            const int kc = i & 3;
            const uint32_t so = off_swz(m, kc);
            const int n = col0 + m;
            const long long bo = (long long)(n < N ? n : 0) * ldb + kc * 8;
            const int sz = (n < N) ? 16 : 0;
            CP_ASYNC16(base + 2 * BUFA + so,        BgH + bo, sz);
            CP_ASYNC16(base + 2 * BUFA + BUFB + so, BgL + bo, sz);
        }
        CP_COMMIT();
    };

    float acc[NMI][NFR][4];
#pragma unroll
    for (int i = 0; i < NMI; i++)
#pragma unroll
        for (int j = 0; j < NFR; j++)
#pragma unroll
            for (int e = 0; e < 4; e++) acc[i][j][e] = 0.f;

    // Preload + pad to exactly NSTAGE-1 pending groups.
    const int PRE = (KT < NSTAGE - 1) ? KT : (NSTAGE - 1);
    for (int kt = 0; kt < PRE; kt++) load_stage(kt);
    for (int e = PRE; e < NSTAGE - 1; e++) CP_COMMIT();

    for (int kt = 0; kt < KT; kt++) {
        CP_WAIT(NSTAGE - 2);
        __syncthreads();

        const uint32_t sb   = sbase + (uint32_t)(kt % NSTAGE) * STB;
        const uint32_t aHiB = sb;
        const uint32_t aLoB = sb + BUFA;
        const uint32_t bHiB = sb + 2 * BUFA;
        const uint32_t bLoB = sb + 2 * BUFA + BUFB;

#pragma unroll
        for (int ks = 0; ks < 2; ks++) {
            const int kcb = ks * 2;
            // ---- burst of B-fragment LDSMs ----
            unsigned bh[NFR][2], bl[NFR][2];
#pragma unroll
            for (int hB = 0; hB < NLD; hB++) {
                const uint32_t so = off_swz(n0 + hB * 16 + bn_l, kcb + bk_l);
                LDSM4(bh[2*hB][0], bh[2*hB][1], bh[2*hB+1][0], bh[2*hB+1][1], bHiB + so);
                LDSM4(bl[2*hB][0], bl[2*hB][1], bl[2*hB+1][0], bl[2*hB+1][1], bLoB + so);
            }
            if constexpr (NMI <= 3) {
                // A double-buffered pipeline (fits reg budget at NMI<=3)
                unsigned ah[2][4], al[2][4];
                {
                    const uint32_t so = off_swz(m0 + am_l, kcb + ak_l);
                    LDSM4(ah[0][0], ah[0][1], ah[0][2], ah[0][3], aHiB + so);
                    LDSM4(al[0][0], al[0][1], al[0][2], al[0][3], aLoB + so);
                }
#pragma unroll
                for (int mi = 0; mi < NMI; mi++) {
                    const int cur = mi & 1;
                    if (mi + 1 < NMI) {
                        const uint32_t so = off_swz(m0 + (mi + 1) * 16 + am_l, kcb + ak_l);
                        LDSM4(ah[cur ^ 1][0], ah[cur ^ 1][1], ah[cur ^ 1][2], ah[cur ^ 1][3], aHiB + so);
                        LDSM4(al[cur ^ 1][0], al[cur ^ 1][1], al[cur ^ 1][2], al[cur ^ 1][3], aLoB + so);
                    }
#pragma unroll
                    for (int ni = 0; ni < NFR; ni++) {
                        mma_bf16(acc[mi][ni], ah[cur], bh[ni]);
                        mma_bf16(acc[mi][ni], ah[cur], bl[ni]);
                        mma_bf16(acc[mi][ni], al[cur], bh[ni]);
                    }
                }
            } else {
                // NMI=4: single-buffered A (keeps regs < 128, no spill)
#pragma unroll
                for (int mi = 0; mi < NMI; mi++) {
                    unsigned ah[4], al[4];
                    const uint32_t so = off_swz(m0 + mi * 16 + am_l, kcb + ak_l);
                    LDSM4(ah[0], ah[1], ah[2], ah[3], aHiB + so);
                    LDSM4(al[0], al[1], al[2], al[3], aLoB + so);
#pragma unroll
                    for (int ni = 0; ni < NFR; ni++) {
                        mma_bf16(acc[mi][ni], ah, bh[ni]);
                        mma_bf16(acc[mi][ni], ah, bl[ni]);
                        mma_bf16(acc[mi][ni], al, bh[ni]);
                    }
                }
            }
            if (ks == 0) {                       // prefetch overlaps ks1 tensor work
                const int pf = kt + NSTAGE - 1;
                if (pf < KT) load_stage(pf); else CP_COMMIT();
            }
        }
    }
    CP_WAIT(0);

    // ---------------- epilogue -----------------------------------------------
#pragma unroll
    for (int mi = 0; mi < NMI; mi++) {
#pragma unroll
        for (int ni = 0; ni < NFR; ni++) {
            const int n = col0 + n0 + ni * 8 + 2 * c;
#pragma unroll
            for (int h = 0; h < 2; h++) {
                const int r = row0 + m0 + mi * 16 + g + h * 8;
                float v0 = alpha * acc[mi][ni][2 * h];
                float v1 = alpha * acc[mi][ni][2 * h + 1];
                if (flags & 4) {
                    if (n + 1 < N)
                        *reinterpret_cast<float2*>(&Cf[(long long)r * ldc + n]) =
                            make_float2(v0, v1);
                    else if (n < N) Cf[(long long)r * ldc + n] = v0;
                } else {
                    unsigned uh, ul;
                    pack2(v0, v1, uh, ul);
                    const long long o = (long long)r * ldc + n;
                    if (n + 1 < N) {
                        *reinterpret_cast<unsigned*>(&Chi[o]) = uh;
                        *reinterpret_cast<unsigned*>(&Clo[o]) = ul;
                    } else if (n < N) {
                        Chi[o] = __float2bfloat16(v0);
                        Clo[o] = __float2bfloat16(v0 - __bfloat162float(__float2bfloat16(v0)));
                    }
                }
            }
        }
    }
    // fused k_pe broadcast into C cols [DN_, DN_+64)  (K_eff GEMM only)
    if (flags & 8) {
#pragma unroll 4
        for (int i = tid; i < TM * 8; i += 256) {
            const int r  = i >> 3;
            const int c8 = i & 7;
            const long long src = (long long)(row0 + r) * DF_ + KVL_ + c8 * 8;
            const long long dst = (long long)(row0 + r) * ldc + DN_ + c8 * 8;
            *reinterpret_cast<uint4*>(&Chi[dst]) = *reinterpret_cast<const uint4*>(&KpeH[src]);
            *reinterpret_cast<uint4*>(&Clo[dst]) = *reinterpret_cast<const uint4*>(&KpeL[src]);
        }
    }
}

// ---------------- fp32 -> (hi, lo) split -------------------------------------
__global__ void split_f32(const float* __restrict__ x, bf16* __restrict__ hi,
                          bf16* __restrict__ lo, long long n)
{
    long long i = (long long)blockIdx.x * blockDim.x + threadIdx.x;
    if (i >= n) return;
    float v = x[i];
    bf16 h = __float2bfloat16(v);
    hi[i] = h;
    lo[i] = __float2bfloat16(v - __bfloat162float(h));
}

// ---------------- fp32 transpose -> K-major (hi, lo) -------------------------
__global__ void transpose_split(const float* __restrict__ X, bf16* __restrict__ Thi,
                                bf16* __restrict__ Tlo, int R, int C, int ldx,
                                long long sX, long long sT)
{
    __shared__ float t[32][33];
    X   += (long long)blockIdx.z * sX;
    Thi += (long long)blockIdx.z * sT;
    Tlo += (long long)blockIdx.z * sT;
    const int c0 = blockIdx.x * 32, r0 = blockIdx.y * 32;
    const int tx = threadIdx.x, ty = threadIdx.y;
#pragma unroll
    for (int i = 0; i < 32; i += 8) {
        int r = r0 + ty + i;
        if (r < R && c0 + tx < C) t[ty + i][tx] = X[(long long)r * ldx + c0 + tx];
    }
    __syncthreads();
#pragma unroll
    for (int i = 0; i < 32; i += 8) {
        int cc = c0 + ty + i;
        if (cc < C && r0 + tx < R) {
            float v = t[tx][ty + i];
            long long o = (long long)cc * R + r0 + tx;
            bf16 h = __float2bfloat16(v);
            Thi[o] = h;
            Tlo[o] = __float2bfloat16(v - __bfloat162float(h));
        }
    }
}

// ---------------- RMSNorm (pair in place, vectorized) -----------------------
__global__ __launch_bounds__(256) void rmsnorm_q(bf16* __restrict__ xh,
                                                 bf16* __restrict__ xl,
                                                 const float* __restrict__ w)
{
    const int s = blockIdx.x;
    const long long base = (long long)s * QL_;
    const int tid = threadIdx.x;
    const int t = tid * 8;
    __shared__ float red[256];
    float f[8];
    float ss = 0.f;
    if (t < QL_) {
        uint4 vh = *reinterpret_cast<const uint4*>(&xh[base + t]);
        uint4 vl = *reinterpret_cast<const uint4*>(&xl[base + t]);
        unpack2(vh.x, vl.x, f[0], f[1]);
        unpack2(vh.y, vl.y, f[2], f[3]);
        unpack2(vh.z, vl.z, f[4], f[5]);
        unpack2(vh.w, vl.w, f[6], f[7]);
#pragma unroll
        for (int j = 0; j < 8; j++) ss += f[j] * f[j];
    }
    red[tid] = ss; __syncthreads();
    for (int off = 128; off > 0; off >>= 1) {
        if (tid < off) red[tid] += red[tid + off];
        __syncthreads();
    }
    const float inv = rsqrtf(red[0] / QL_ + 1e-6f) * SCALE_Q_;
    if (t < QL_) {
        unsigned uh[4], ul[4];
#pragma unroll
        for (int p = 0; p < 4; p++) {
            float a = w[t + 2 * p] * f[2 * p] * inv;
            float b = w[t + 2 * p + 1] * f[2 * p + 1] * inv;
            pack2(a, b, uh[p], ul[p]);
        }
        *reinterpret_cast<uint4*>(&xh[base + t]) = make_uint4(uh[0], uh[1], uh[2], uh[3]);
        *reinterpret_cast<uint4*>(&xl[base + t]) = make_uint4(ul[0], ul[1], ul[2], ul[3]);
    }
}

// ---------------- kva RMSNorm + k_pe RoPE -> k_full (pairs) ------------------
__global__ void kva_norm_rope(const bf16* __restrict__ lh, const bf16* __restrict__ ll,
                              const float* __restrict__ w,
                              const float* __restrict__ cosb, const float* __restrict__ sinb,
                              bf16* __restrict__ kh, bf16* __restrict__ kl)
{
    const int s = blockIdx.x;
    const int tid = threadIdx.x;           // 128 threads
    const long long base = (long long)s * DF_;
    __shared__ float red[128];
    float ss = 0.f;
    for (int j = tid; j < KVL_; j += 128) { float v = pget(lh, ll, base + j); ss += v * v; }
    red[tid] = ss; __syncthreads();
    for (int off = 64; off > 0; off >>= 1) {
        if (tid < off) red[tid] += red[tid + off];
        __syncthreads();
    }
    const float inv = rsqrtf(red[0] / KVL_ + 1e-6f) * SCALE_KV_;
    for (int j = tid; j < KVL_; j += 128)
        pset(kh, kl, base + j, w[j] * pget(lh, ll, base + j) * inv);
    if (tid < DR_) {
        const int r = tid;
        float x = pget(lh, ll, base + KVL_ + r);
        float o = (r < 32) ? -pget(lh, ll, base + KVL_ + r + 32)
                           :  pget(lh, ll, base + KVL_ + r - 32);
        pset(kh, kl, base + KVL_ + r, x * cosb[s * DR_ + r] + o * sinb[s * DR_ + r]);
    }
}

// ---------------- q_pe RoPE in place (pair-safe) -----------------------------
__global__ void rope_q_inplace(bf16* __restrict__ qh, bf16* __restrict__ ql,
                               const float* __restrict__ cosb, const float* __restrict__ sinb)
{
    long long idx = (long long)blockIdx.x * blockDim.x + threadIdx.x;
    if (idx >= (long long)S_ * NH_ * 32) return;
    const int r2 = (int)(idx % 32);
    const int h  = (int)((idx / 32) % NH_);
    const int s  = (int)(idx / (32LL * NH_));
    const long long base = (long long)s * NH_ * QDIM_ + h * QDIM_ + DN_;
    float x1 = pget(qh, ql, base + r2);
    float x2 = pget(qh, ql, base + 32 + r2);
    const float c1 = cosb[s * DR_ + r2],      s1 = sinb[s * DR_ + r2];
    const float c2 = cosb[s * DR_ + 32 + r2], s2 = sinb[s * DR_ + 32 + r2];
    pset(qh, ql, base + r2,      x1 * c1 - x2 * s1);
    pset(qh, ql, base + 32 + r2, x2 * c2 + x1 * s2);
}

// ------- causal softmax: fp32 in, (hi,lo) pairs out, 256 threads -------------
__global__ __launch_bounds__(256) void softmax_causal(const float* __restrict__ sf,
                                                      bf16* __restrict__ sh,
                                                      bf16* __restrict__ sl)
{
    const int s = blockIdx.x, h = blockIdx.y;
    const long long base = ((long long)h * S_ + s) * (long long)S_;
    __shared__ float vals[S_];
    __shared__ float red[256];
    const int tid = threadIdx.x;
    const int len = s + 1;
    const int len4 = len & ~3;

    float m = -1e30f;
    for (int t = tid * 4; t < len4; t += 1024) {
        float4 v = *reinterpret_cast<const float4*>(&sf[base + t]);
        vals[t] = v.x; vals[t + 1] = v.y; vals[t + 2] = v.z; vals[t + 3] = v.w;
        m = fmaxf(fmaxf(m, fmaxf(v.x, v.y)), fmaxf(v.z, v.w));
    }
    for (int t = len4 + tid; t < len; t += 256) {
        float v = sf[base + t];
        vals[t] = v; m = fmaxf(m, v);
    }
    red[tid] = m; __syncthreads();
    for (int off = 128; off > 0; off >>= 1) {
        if (tid < off) red[tid] = fmaxf(red[tid], red[tid + off]);
        __syncthreads();
    }
    m = red[0]; __syncthreads();

    float sum = 0.f;
    for (int t = tid; t < len; t += 256) {
        float e = __expf(vals[t] - m);
        vals[t] = e; sum += e;
    }
    red[tid] = sum; __syncthreads();
    for (int off = 128; off > 0; off >>= 1) {
        if (tid < off) red[tid] += red[tid + off];
        __syncthreads();
    }
    const float inv = 1.f / red[0];

    const int rowEnd = (s & ~63) + 64;   // out_v GEMM (TM=64) reads k < rowEnd
    for (int t = tid * 8; t < rowEnd; t += 2048) {
        unsigned uh[4], ul[4];
#pragma unroll
        for (int p = 0; p < 4; p++) {
            float a = (t + 2 * p     < len) ? vals[t + 2 * p] * inv : 0.f;
            float b = (t + 2 * p + 1 < len) ? vals[t + 2 * p + 1] * inv : 0.f;
            pack2(a, b, uh[p], ul[p]);
        }
        *reinterpret_cast<uint4*>(&sh[base + t]) = make_uint4(uh[0], uh[1], uh[2], uh[3]);
        *reinterpret_cast<uint4*>(&sl[base + t]) = make_uint4(ul[0], ul[1], ul[2], ul[3]);
    }
}

// =============================================================================
extern "C" void kernel_launch(void* const* d_in, const int* in_sizes, int n_in,
                              void* d_out, int out_size)
{
    const float* hidden = (const float*)d_in[0];
    const float* cosb   = (const float*)d_in[1];
    const float* sinb   = (const float*)d_in[2];
    const float* w_qa   = (const float*)d_in[3];
    const float* qa_ln  = (const float*)d_in[4];
    const float* w_qb   = (const float*)d_in[5];
    const float* w_kva  = (const float*)d_in[6];
    const float* kva_ln = (const float*)d_in[7];
    const float* w_k    = (const float*)d_in[8];
    const float* w_v    = (const float*)d_in[9];
    const float* w_o    = (const float*)d_in[10];
    float* out = (float*)d_out;

    bf16 *hid, *qlat, *q, *lat, *kf, *kcat, *veff, *sc, *ao;
    bf16 *wqa, *wqb, *wkva, *wk, *wvT, *woT;
    float *scf;
    cudaGetSymbolAddress((void**)&hid,  g_hid2);
    cudaGetSymbolAddress((void**)&qlat, g_qlat2);
    cudaGetSymbolAddress((void**)&q,    g_q2);
    cudaGetSymbolAddress((void**)&lat,  g_lat2);
    cudaGetSymbolAddress((void**)&kf,   g_kf2);
    cudaGetSymbolAddress((void**)&kcat, g_kcat2);
    cudaGetSymbolAddress((void**)&veff, g_veff2);
    cudaGetSymbolAddress((void**)&sc,   g_sc2);
    cudaGetSymbolAddress((void**)&scf,  g_scf);
    cudaGetSymbolAddress((void**)&ao,   g_ao2);
    cudaGetSymbolAddress((void**)&wqa,  g_wqa2);
    cudaGetSymbolAddress((void**)&wqb,  g_wqb2);
    cudaGetSymbolAddress((void**)&wkva, g_wkva2);
    cudaGetSymbolAddress((void**)&wk,   g_wk2);
    cudaGetSymbolAddress((void**)&wvT,  g_wv2);
    cudaGetSymbolAddress((void**)&woT,  g_wo2);

    bf16 *hidL = hid + N_HID,  *qlatL = qlat + N_QLAT, *qL = q + N_Q;
    bf16 *latL = lat + N_LAT,  *kfL = kf + N_KF;
    bf16 *kcatL = kcat + N_KCAT, *veffL = veff + N_VEFF;
    bf16 *scL  = sc + N_SC,    *aoL = ao + N_AO;
    bf16 *wqaL = wqa + N_WQA,  *wqbL = wqb + N_WQB,    *wkvaL = wkva + N_WKVA;
    bf16 *wkL  = wk + N_WK,    *wvTL = wvT + N_WV,     *woTL = woT + N_WO;

    constexpr int SM64_4 = 4 * (2 * 64 * 64 + 2 * 128 * 64);   // 98304
    constexpr int SM96_4 = 4 * (2 * 96 * 64 + 2 * 128 * 64);   // 114688
    cudaFuncSetAttribute((void*)mma_gemm<64, 128, 4>, cudaFuncAttributeMaxDynamicSharedMemorySize, SM64_4);
    cudaFuncSetAttribute((void*)mma_gemm<96, 128, 4>, cudaFuncAttributeMaxDynamicSharedMemorySize, SM96_4);

    const dim3 tb(32, 8);

    // weight prep
    transpose_split<<<dim3(QL_ / 32, HID_ / 32, 1), tb>>>(w_qa, wqa, wqaL, HID_, QL_, QL_, 0, 0);
    transpose_split<<<dim3(NH_ * QDIM_ / 32, QL_ / 32, 1), tb>>>(w_qb, wqb, wqbL, QL_, NH_ * QDIM_, NH_ * QDIM_, 0, 0);
    // split hidden
    {
        long long n = (long long)N_HID;
        split_f32<<<(unsigned)((n + 255) / 256), 256>>>(hidden, hid, hidL, n);
    }
    // launch 3 (profile slot): q_lat = hidden @ w_qa  (TM=64, NSTAGE=4 - control)
    mma_gemm<64, 128, 4><<<dim3(QL_ / 128, S_ / 64, 1), 256, SM64_4>>>(
        hid, hidL, wqa, wqaL, qlat, qlatL, nullptr, nullptr, nullptr,
        S_, QL_, HID_, HID_, HID_, QL_, 0, 0, 0, 1.f, 0);
    rmsnorm_q<<<S_, 256>>>(qlat, qlatL, qa_ln);
    // q = q_lat @ w_qb   (TM=96, NSTAGE=4)
    mma_gemm<96, 128, 4><<<dim3(NH_ * QDIM_ / 128, S_ / 96, 1), 256, SM96_4>>>(
        qlat, qlatL, wqb, wqbL, q, qL, nullptr, nullptr, nullptr,
        S_, NH_ * QDIM_, QL_, QL_, QL_, NH_ * QDIM_, 0, 0, 0, 1.f, 0);
    // rope q_pe in place
    {
        long long tot = (long long)S_ * NH_ * 32;
        rope_q_inplace<<<(unsigned)((tot + 255) / 256), 256>>>(q, qL, cosb, sinb);
    }
    // latent path (TM=64, NSTAGE=4)
    transpose_split<<<dim3(DF_ / 32, HID_ / 32, 1), tb>>>(w_kva, wkva, wkvaL, HID_, DF_, DF_, 0, 0);
    mma_gemm<64, 128, 4><<<dim3((DF_ + 127) / 128, S_ / 64, 1), 256, SM64_4>>>(
        hid, hidL, wkva, wkvaL, lat, latL, nullptr, nullptr, nullptr,
        S_, DF_, HID_, HID_, HID_, DF_, 0, 0, 0, 1.f, 0);
    kva_norm_rope<<<S_, 128>>>(lat, latL, kva_ln, cosb, sinb, kf, kfL);

    // ---- K_eff + fused pe broadcast: kcat[h][t][:]  (TM=96) ----
    {
        long long n = (long long)N_WK;
        split_f32<<<(unsigned)((n + 255) / 256), 256>>>(w_k, wk, wkL, n);
    }
    mma_gemm<96, 128, 4><<<dim3(1, S_ / 96, NH_), 256, SM96_4>>>(
        kf, kfL, wk, wkL, kcat, kcatL, nullptr, kf, kfL,
        S_, DN_, KVL_, DF_, KVL_, KCAT_,
        0LL, (long long)DN_ * KVL_, (long long)S_ * KCAT_, 1.f, 8);
    // ---- V_eff^T[h] = w_v[h]^T @ c_kv^T  (TM=64; M=128) ----
    transpose_split<<<dim3(DV_ / 32, KVL_ / 32, NH_), tb>>>(w_v, wvT, wvTL, KVL_, DV_, DV_,
        (long long)KVL_ * DV_, (long long)DV_ * KVL_);
    mma_gemm<64, 128, 4><<<dim3(S_ / 128, DV_ / 64, NH_), 256, SM64_4>>>(
        wvT, wvTL, kf, kfL, veff, veffL, nullptr, nullptr, nullptr,
        DV_, S_, KVL_, KVL_, DF_, S_,
        (long long)DV_ * KVL_, 0LL, (long long)DV_ * S_, 1.f, 0);

    // ---- scores = SM_SCALE * q[h] @ kcat[h]^T  (K=192, causal skip, TM=96) --
    mma_gemm<96, 128, 4><<<dim3(S_ / 128, S_ / 96, NH_), 256, SM96_4>>>(
        q, qL, kcat, kcatL, nullptr, nullptr, scf, nullptr, nullptr,
        S_, S_, KCAT_, NH_ * QDIM_, KCAT_, S_,
        (long long)QDIM_, (long long)S_ * KCAT_, (long long)S_ * S_, SM_SCALE_, 1 | 4);
    // softmax (rowEnd 64-block, matches out_v TM=64)
    softmax_causal<<<dim3(S_, NH_), 256>>>(scf, sc, scL);
    // ---- ao[:, h*128:+128] = attn[h] @ V_eff[h]  (TM=64, K-limit row0+64) ----
    mma_gemm<64, 128, 4><<<dim3(1, S_ / 64, NH_), 256, SM64_4>>>(
        sc, scL, veff, veffL, ao, aoL, nullptr, nullptr, nullptr,
        S_, DV_, S_, S_, S_, NH_ * DV_,
        (long long)S_ * S_, (long long)DV_ * S_, (long long)DV_, 1.f, 2);
    // out = ao @ w_o  (TM=96, NSTAGE=4)
    transpose_split<<<dim3(HID_ / 32, (NH_ * DV_) / 32, 1), tb>>>(w_o, woT, woTL, NH_ * DV_, HID_, HID_, 0, 0);
    mma_gemm<96, 128, 4><<<dim3(HID_ / 128, S_ / 96, 1), 256, SM96_4>>>(
        ao, aoL, woT, woTL, nullptr, nullptr, out, nullptr, nullptr,
        S_, HID_, NH_ * DV_, NH_ * DV_, NH_ * DV_, HID_, 0, 0, 0, 1.f, 4);
}

// round 17
// speedup vs baseline: 1.0422x; 1.0422x over previous
#include <cuda_runtime.h>
#include <cuda_bf16.h>
#include <cstdint>
#include <math.h>

#define S_    1536
#define HID_  6144
#define NH_   64
#define DN_   128
#define DR_   64
#define DV_   128
#define QL_   1536
#define KVL_  512
#define DF_   576        // KVL + DR
#define QDIM_ 192        // DN + DR
#define KCAT_ 192        // DN + DR (scores K)

#define SM_SCALE_  0.07216878364870322f
#define SCALE_Q_   2.0f
#define SCALE_KV_  3.4641016151377544f

#define KC 32

typedef __nv_bfloat16 bf16;

// ---------------- scratch: activations/weights as (hi, lo) bf16 pairs -------
#define N_HID  ((size_t)S_ * HID_)
#define N_QLAT ((size_t)S_ * QL_)
#define N_Q    ((size_t)S_ * NH_ * QDIM_)
#define N_LAT  ((size_t)S_ * DF_)
#define N_KF   ((size_t)S_ * DF_)
#define N_KCAT ((size_t)NH_ * S_ * KCAT_)
#define N_VEFF ((size_t)NH_ * DV_ * S_)
#define N_SC   ((size_t)NH_ * S_ * S_)
#define N_AO   ((size_t)S_ * NH_ * DV_)
#define N_WQA  ((size_t)QL_ * HID_)
#define N_WQB  ((size_t)NH_ * QDIM_ * QL_)
#define N_WKVA ((size_t)DF_ * HID_)
#define N_WK   ((size_t)NH_ * DN_ * KVL_)
#define N_WV   ((size_t)NH_ * DV_ * KVL_)
#define N_WO   ((size_t)HID_ * NH_ * DV_)

__device__ __align__(256) unsigned short g_hid2 [2 * N_HID];
__device__ __align__(256) unsigned short g_qlat2[2 * N_QLAT];
__device__ __align__(256) unsigned short g_q2   [2 * N_Q];
__device__ __align__(256) unsigned short g_lat2 [2 * N_LAT];
__device__ __align__(256) unsigned short g_kf2  [2 * N_KF];
__device__ __align__(256) unsigned short g_kcat2[2 * N_KCAT];
__device__ __align__(256) unsigned short g_veff2[2 * N_VEFF];
__device__ __align__(256) unsigned short g_sc2  [2 * N_SC];
__device__ __align__(256) float          g_scf  [N_SC];
__device__ __align__(256) unsigned short g_ao2  [2 * N_AO];
__device__ __align__(256) unsigned short g_wqa2 [2 * N_WQA];
__device__ __align__(256) unsigned short g_wqb2 [2 * N_WQB];
__device__ __align__(256) unsigned short g_wkva2[2 * N_WKVA];
__device__ __align__(256) unsigned short g_wk2  [2 * N_WK];
__device__ __align__(256) unsigned short g_wv2  [2 * N_WV];
__device__ __align__(256) unsigned short g_wo2  [2 * N_WO];

// ---------------- helpers ----------------------------------------------------
__device__ __forceinline__ uint32_t smem_u32(const void* p) {
    uint32_t a;
    asm("{ .reg .u64 t; cvta.to.shared.u64 t, %1; cvt.u32.u64 %0, t; }" : "=r"(a) : "l"(p));
    return a;
}
#define CP_ASYNC16(dst, src, sz) \
    asm volatile("cp.async.cg.shared.global [%0], [%1], 16, %2;" :: "r"(dst), "l"(src), "r"(sz))
#define CP_COMMIT() asm volatile("cp.async.commit_group;" ::: "memory")
#define CP_WAIT(n)  asm volatile("cp.async.wait_group %0;" :: "n"(n) : "memory")

#define LDSM4(r0, r1, r2, r3, a) \
    asm volatile("ldmatrix.sync.aligned.m8n8.x4.shared.b16 {%0,%1,%2,%3}, [%4];" \
                 : "=r"(r0), "=r"(r1), "=r"(r2), "=r"(r3) : "r"(a))

__device__ __forceinline__ void mma_bf16(float* d, const unsigned* a, const unsigned* b) {
    asm volatile(
        "mma.sync.aligned.m16n8k16.row.col.f32.bf16.bf16.f32 "
        "{%0,%1,%2,%3}, {%4,%5,%6,%7}, {%8,%9}, {%0,%1,%2,%3};"
        : "+f"(d[0]), "+f"(d[1]), "+f"(d[2]), "+f"(d[3])
        : "r"(a[0]), "r"(a[1]), "r"(a[2]), "r"(a[3]), "r"(b[0]), "r"(b[1]));
}

__device__ __forceinline__ uint32_t off_swz(int row, int kc) {
    return (uint32_t)(row >> 1) * 128u +
           (uint32_t)(((((row & 1) << 2) + kc) ^ ((row >> 1) & 7)) * 16);
}

__device__ __forceinline__ float pget(const bf16* h, const bf16* l, long long i) {
    return __bfloat162float(h[i]) + __bfloat162float(l[i]);
}
__device__ __forceinline__ void pset(bf16* h, bf16* l, long long i, float v) {
    bf16 a = __float2bfloat16(v);
    h[i] = a;
    l[i] = __float2bfloat16(v - __bfloat162float(a));
}
__device__ __forceinline__ void unpack2(unsigned h, unsigned l, float& a, float& b) {
    a = __uint_as_float(h << 16) + __uint_as_float(l << 16);
    b = __uint_as_float(h & 0xffff0000u) + __uint_as_float(l & 0xffff0000u);
}
__device__ __forceinline__ void pack2(float a, float b, unsigned& h, unsigned& l) {
    bf16 ha = __float2bfloat16(a), hb = __float2bfloat16(b);
    bf16 la = __float2bfloat16(a - __bfloat162float(ha));
    bf16 lb = __float2bfloat16(b - __bfloat162float(hb));
    __nv_bfloat162 hv; hv.x = ha; hv.y = hb;
    __nv_bfloat162 lv; lv.x = la; lv.y = lb;
    h = *reinterpret_cast<unsigned*>(&hv);
    l = *reinterpret_cast<unsigned*>(&lv);
}

// flags: bit0 causal tile skip, bit1 K limited to row0+TM, bit2 fp32 C,
//        bit3 epilogue also copies roped k_pe into C cols [DN_, DN_+64)
template <int TM, int TN, int NSTAGE>
__global__ __launch_bounds__(256, 2) void mma_gemm(
    const bf16* __restrict__ Ahi, const bf16* __restrict__ Alo,
    const bf16* __restrict__ Bhi, const bf16* __restrict__ Blo,
    bf16* __restrict__ Chi, bf16* __restrict__ Clo, float* __restrict__ Cf,
    const bf16* __restrict__ KpeH, const bf16* __restrict__ KpeL,
    int M, int N, int K, int lda, int ldb, int ldc,
    long long sA, long long sB, long long sC, float alpha, int flags)
{
    constexpr uint32_t BUFA = (uint32_t)TM * 64u;
    constexpr uint32_t BUFB = (uint32_t)TN * 64u;
    constexpr uint32_t STB  = 2u * BUFA + 2u * BUFB;
    constexpr int NFR = TN / 32;
    constexpr int NLD = TN / 64;
    constexpr int NMI = TM / 32;

    const int row0 = blockIdx.y * TM;
    const int col0 = blockIdx.x * TN;
    if ((flags & 1) && col0 >= row0 + TM) return;

    const long long bz = blockIdx.z;
    Ahi += bz * sA;  Alo += bz * sA;
    Bhi += bz * sB;  Blo += bz * sB;
    if (flags & 4) Cf += bz * sC; else { Chi += bz * sC; Clo += bz * sC; }

    const int Keff = (flags & 2) ? min(K, row0 + TM) : K;
    const int KT = Keff / KC;

    extern __shared__ char smraw[];
    const uint32_t sbase = smem_u32(smraw);
    const int tid  = threadIdx.x;
    const int wid  = tid >> 5;
    const int lane = tid & 31;
    const int g    = lane >> 2;
    const int c    = lane & 3;
    const int m0   = (wid & 1) * (TM / 2);
    const int n0   = (wid >> 1) * (TN / 4);

    const int am_l = (lane & 7) + ((lane >> 3) & 1) * 8;
    const int ak_l = lane >> 4;
    const int bn_l = (lane & 7) + ((lane >> 4) & 1) * 8;
    const int bk_l = (lane >> 3) & 1;

    auto load_stage = [&](int kt) {
        const uint32_t base = sbase + (uint32_t)(kt % NSTAGE) * STB;
        const bf16* AgH = Ahi + (long long)row0 * lda + (long long)kt * KC;
        const bf16* AgL = Alo + (long long)row0 * lda + (long long)kt * KC;
        const bf16* BgH = Bhi + (long long)kt * KC;
        const bf16* BgL = Blo + (long long)kt * KC;
#pragma unroll
        for (int i = tid; i < TM * 4; i += 256) {
            const int m  = i >> 2;
            const int kc = i & 3;
            const uint32_t so = off_swz(m, kc);
            CP_ASYNC16(base + so,        AgH + (long long)m * lda + kc * 8, 16);
            CP_ASYNC16(base + BUFA + so, AgL + (long long)m * lda + kc * 8, 16);
        }
#pragma unroll
        for (int i = tid; i < TN * 4; i += 256) {
            const int m  = i >> 2;
            const int kc = i & 3;
            const uint32_t so = off_swz(m, kc);
            const int n = col0 + m;
            const long long bo = (long long)(n < N ? n : 0) * ldb + kc * 8;
            const int sz = (n < N) ? 16 : 0;
            CP_ASYNC16(base + 2 * BUFA + so,        BgH + bo, sz);
            CP_ASYNC16(base + 2 * BUFA + BUFB + so, BgL + bo, sz);
        }
        CP_COMMIT();
    };

    float acc[NMI][NFR][4];
#pragma unroll
    for (int i = 0; i < NMI; i++)
#pragma unroll
        for (int j = 0; j < NFR; j++)
#pragma unroll
            for (int e = 0; e < 4; e++) acc[i][j][e] = 0.f;

    // Preload + pad to exactly NSTAGE-1 pending groups.
    const int PRE = (KT < NSTAGE - 1) ? KT : (NSTAGE - 1);
    for (int kt = 0; kt < PRE; kt++) load_stage(kt);
    for (int e = PRE; e < NSTAGE - 1; e++) CP_COMMIT();

    for (int kt = 0; kt < KT; kt++) {
        CP_WAIT(NSTAGE - 2);
        __syncthreads();

        const uint32_t sb   = sbase + (uint32_t)(kt % NSTAGE) * STB;
        const uint32_t aHiB = sb;
        const uint32_t aLoB = sb + BUFA;
        const uint32_t bHiB = sb + 2 * BUFA;
        const uint32_t bLoB = sb + 2 * BUFA + BUFB;

#pragma unroll
        for (int ks = 0; ks < 2; ks++) {
            const int kcb = ks * 2;
            // ---- burst of B-fragment LDSMs ----
            unsigned bh[NFR][2], bl[NFR][2];
#pragma unroll
            for (int hB = 0; hB < NLD; hB++) {
                const uint32_t so = off_swz(n0 + hB * 16 + bn_l, kcb + bk_l);
                LDSM4(bh[2*hB][0], bh[2*hB][1], bh[2*hB+1][0], bh[2*hB+1][1], bHiB + so);
                LDSM4(bl[2*hB][0], bl[2*hB][1], bl[2*hB+1][0], bl[2*hB+1][1], bLoB + so);
            }
            if constexpr (NMI == 2) {
                // Full A double-buffer (hi+lo) — fits reg budget at NMI=2
                unsigned ah[2][4], al[2][4];
                {
                    const uint32_t so = off_swz(m0 + am_l, kcb + ak_l);
                    LDSM4(ah[0][0], ah[0][1], ah[0][2], ah[0][3], aHiB + so);
                    LDSM4(al[0][0], al[0][1], al[0][2], al[0][3], aLoB + so);
                }
#pragma unroll
                for (int mi = 0; mi < NMI; mi++) {
                    const int cur = mi & 1;
                    if (mi + 1 < NMI) {
                        const uint32_t so = off_swz(m0 + (mi + 1) * 16 + am_l, kcb + ak_l);
                        LDSM4(ah[cur ^ 1][0], ah[cur ^ 1][1], ah[cur ^ 1][2], ah[cur ^ 1][3], aHiB + so);
                        LDSM4(al[cur ^ 1][0], al[cur ^ 1][1], al[cur ^ 1][2], al[cur ^ 1][3], aLoB + so);
                    }
#pragma unroll
                    for (int ni = 0; ni < NFR; ni++) {
                        mma_bf16(acc[mi][ni], ah[cur], bh[ni]);
                        mma_bf16(acc[mi][ni], ah[cur], bl[ni]);
                        mma_bf16(acc[mi][ni], al[cur], bh[ni]);
                    }
                }
            } else {
                // NMI=4: hi-half A double-buffer (+8 regs), lo loaded at use.
                unsigned ah[2][4];
                {
                    const uint32_t so = off_swz(m0 + am_l, kcb + ak_l);
                    LDSM4(ah[0][0], ah[0][1], ah[0][2], ah[0][3], aHiB + so);
                }
#pragma unroll
                for (int mi = 0; mi < NMI; mi++) {
                    const int cur = mi & 1;
                    unsigned al[4];
                    {
                        const uint32_t so = off_swz(m0 + mi * 16 + am_l, kcb + ak_l);
                        LDSM4(al[0], al[1], al[2], al[3], aLoB + so);
                    }
                    if (mi + 1 < NMI) {
                        const uint32_t so = off_swz(m0 + (mi + 1) * 16 + am_l, kcb + ak_l);
                        LDSM4(ah[cur ^ 1][0], ah[cur ^ 1][1], ah[cur ^ 1][2], ah[cur ^ 1][3], aHiB + so);
                    }
#pragma unroll
                    for (int ni = 0; ni < NFR; ni++) {
                        mma_bf16(acc[mi][ni], ah[cur], bh[ni]);
                        mma_bf16(acc[mi][ni], ah[cur], bl[ni]);
                        mma_bf16(acc[mi][ni], al, bh[ni]);
                    }
                }
            }
            if (ks == 0) {                       // prefetch overlaps ks1 tensor work
                const int pf = kt + NSTAGE - 1;
                if (pf < KT) load_stage(pf); else CP_COMMIT();
            }
        }
    }
    CP_WAIT(0);

    // ---------------- epilogue -----------------------------------------------
#pragma unroll
    for (int mi = 0; mi < NMI; mi++) {
#pragma unroll
        for (int ni = 0; ni < NFR; ni++) {
            const int n = col0 + n0 + ni * 8 + 2 * c;
#pragma unroll
            for (int h = 0; h < 2; h++) {
                const int r = row0 + m0 + mi * 16 + g + h * 8;
                float v0 = alpha * acc[mi][ni][2 * h];
                float v1 = alpha * acc[mi][ni][2 * h + 1];
                if (flags & 4) {
                    if (n + 1 < N)
                        *reinterpret_cast<float2*>(&Cf[(long long)r * ldc + n]) =
                            make_float2(v0, v1);
                    else if (n < N) Cf[(long long)r * ldc + n] = v0;
                } else {
                    unsigned uh, ul;
                    pack2(v0, v1, uh, ul);
                    const long long o = (long long)r * ldc + n;
                    if (n + 1 < N) {
                        *reinterpret_cast<unsigned*>(&Chi[o]) = uh;
                        *reinterpret_cast<unsigned*>(&Clo[o]) = ul;
                    } else if (n < N) {
                        Chi[o] = __float2bfloat16(v0);
                        Clo[o] = __float2bfloat16(v0 - __bfloat162float(__float2bfloat16(v0)));
                    }
                }
            }
        }
    }
    // fused k_pe broadcast into C cols [DN_, DN_+64)  (K_eff GEMM only)
    if (flags & 8) {
#pragma unroll 4
        for (int i = tid; i < TM * 8; i += 256) {
            const int r  = i >> 3;
            const int c8 = i & 7;
            const long long src = (long long)(row0 + r) * DF_ + KVL_ + c8 * 8;
            const long long dst = (long long)(row0 + r) * ldc + DN_ + c8 * 8;
            *reinterpret_cast<uint4*>(&Chi[dst]) = *reinterpret_cast<const uint4*>(&KpeH[src]);
            *reinterpret_cast<uint4*>(&Clo[dst]) = *reinterpret_cast<const uint4*>(&KpeL[src]);
        }
    }
}

// ---------------- fp32 -> (hi, lo) split -------------------------------------
__global__ void split_f32(const float* __restrict__ x, bf16* __restrict__ hi,
                          bf16* __restrict__ lo, long long n)
{
    long long i = (long long)blockIdx.x * blockDim.x + threadIdx.x;
    if (i >= n) return;
    float v = x[i];
    bf16 h = __float2bfloat16(v);
    hi[i] = h;
    lo[i] = __float2bfloat16(v - __bfloat162float(h));
}

// ---------------- fp32 transpose -> K-major (hi, lo) -------------------------
__global__ void transpose_split(const float* __restrict__ X, bf16* __restrict__ Thi,
                                bf16* __restrict__ Tlo, int R, int C, int ldx,
                                long long sX, long long sT)
{
    __shared__ float t[32][33];
    X   += (long long)blockIdx.z * sX;
    Thi += (long long)blockIdx.z * sT;
    Tlo += (long long)blockIdx.z * sT;
    const int c0 = blockIdx.x * 32, r0 = blockIdx.y * 32;
    const int tx = threadIdx.x, ty = threadIdx.y;
#pragma unroll
    for (int i = 0; i < 32; i += 8) {
        int r = r0 + ty + i;
        if (r < R && c0 + tx < C) t[ty + i][tx] = X[(long long)r * ldx + c0 + tx];
    }
    __syncthreads();
#pragma unroll
    for (int i = 0; i < 32; i += 8) {
        int cc = c0 + ty + i;
        if (cc < C && r0 + tx < R) {
            float v = t[tx][ty + i];
            long long o = (long long)cc * R + r0 + tx;
            bf16 h = __float2bfloat16(v);
            Thi[o] = h;
            Tlo[o] = __float2bfloat16(v - __bfloat162float(h));
        }
    }
}

// ---------------- RMSNorm (pair in place, vectorized) -----------------------
__global__ __launch_bounds__(256) void rmsnorm_q(bf16* __restrict__ xh,
                                                 bf16* __restrict__ xl,
                                                 const float* __restrict__ w)
{
    const int s = blockIdx.x;
    const long long base = (long long)s * QL_;
    const int tid = threadIdx.x;
    const int t = tid * 8;
    __shared__ float red[256];
    float f[8];
    float ss = 0.f;
    if (t < QL_) {
        uint4 vh = *reinterpret_cast<const uint4*>(&xh[base + t]);
        uint4 vl = *reinterpret_cast<const uint4*>(&xl[base + t]);
        unpack2(vh.x, vl.x, f[0], f[1]);
        unpack2(vh.y, vl.y, f[2], f[3]);
        unpack2(vh.z, vl.z, f[4], f[5]);
        unpack2(vh.w, vl.w, f[6], f[7]);
#pragma unroll
        for (int j = 0; j < 8; j++) ss += f[j] * f[j];
    }
    red[tid] = ss; __syncthreads();
    for (int off = 128; off > 0; off >>= 1) {
        if (tid < off) red[tid] += red[tid + off];
        __syncthreads();
    }
    const float inv = rsqrtf(red[0] / QL_ + 1e-6f) * SCALE_Q_;
    if (t < QL_) {
        unsigned uh[4], ul[4];
#pragma unroll
        for (int p = 0; p < 4; p++) {
            float a = w[t + 2 * p] * f[2 * p] * inv;
            float b = w[t + 2 * p + 1] * f[2 * p + 1] * inv;
            pack2(a, b, uh[p], ul[p]);
        }
        *reinterpret_cast<uint4*>(&xh[base + t]) = make_uint4(uh[0], uh[1], uh[2], uh[3]);
        *reinterpret_cast<uint4*>(&xl[base + t]) = make_uint4(ul[0], ul[1], ul[2], ul[3]);
    }
}

// ---------------- kva RMSNorm + k_pe RoPE -> k_full (pairs) ------------------
__global__ void kva_norm_rope(const bf16* __restrict__ lh, const bf16* __restrict__ ll,
                              const float* __restrict__ w,
                              const float* __restrict__ cosb, const float* __restrict__ sinb,
                              bf16* __restrict__ kh, bf16* __restrict__ kl)
{
    const int s = blockIdx.x;
    const int tid = threadIdx.x;           // 128 threads
    const long long base = (long long)s * DF_;
    __shared__ float red[128];
    float ss = 0.f;
    for (int j = tid; j < KVL_; j += 128) { float v = pget(lh, ll, base + j); ss += v * v; }
    red[tid] = ss; __syncthreads();
    for (int off = 64; off > 0; off >>= 1) {
        if (tid < off) red[tid] += red[tid + off];
        __syncthreads();
    }
    const float inv = rsqrtf(red[0] / KVL_ + 1e-6f) * SCALE_KV_;
    for (int j = tid; j < KVL_; j += 128)
        pset(kh, kl, base + j, w[j] * pget(lh, ll, base + j) * inv);
    if (tid < DR_) {
        const int r = tid;
        float x = pget(lh, ll, base + KVL_ + r);
        float o = (r < 32) ? -pget(lh, ll, base + KVL_ + r + 32)
                           :  pget(lh, ll, base + KVL_ + r - 32);
        pset(kh, kl, base + KVL_ + r, x * cosb[s * DR_ + r] + o * sinb[s * DR_ + r]);
    }
}

// ---------------- q_pe RoPE in place (pair-safe) -----------------------------
__global__ void rope_q_inplace(bf16* __restrict__ qh, bf16* __restrict__ ql,
                               const float* __restrict__ cosb, const float* __restrict__ sinb)
{
    long long idx = (long long)blockIdx.x * blockDim.x + threadIdx.x;
    if (idx >= (long long)S_ * NH_ * 32) return;
    const int r2 = (int)(idx % 32);
    const int h  = (int)((idx / 32) % NH_);
    const int s  = (int)(idx / (32LL * NH_));
    const long long base = (long long)s * NH_ * QDIM_ + h * QDIM_ + DN_;
    float x1 = pget(qh, ql, base + r2);
    float x2 = pget(qh, ql, base + 32 + r2);
    const float c1 = cosb[s * DR_ + r2],      s1 = sinb[s * DR_ + r2];
    const float c2 = cosb[s * DR_ + 32 + r2], s2 = sinb[s * DR_ + 32 + r2];
    pset(qh, ql, base + r2,      x1 * c1 - x2 * s1);
    pset(qh, ql, base + 32 + r2, x2 * c2 + x1 * s2);
}

// ------- causal softmax: fp32 in, (hi,lo) pairs out, 256 threads -------------
__global__ __launch_bounds__(256) void softmax_causal(const float* __restrict__ sf,
                                                      bf16* __restrict__ sh,
                                                      bf16* __restrict__ sl)
{
    const int s = blockIdx.x, h = blockIdx.y;
    const long long base = ((long long)h * S_ + s) * (long long)S_;
    __shared__ float vals[S_];
    __shared__ float red[256];
    const int tid = threadIdx.x;
    const int len = s + 1;
    const int len4 = len & ~3;

    float m = -1e30f;
    for (int t = tid * 4; t < len4; t += 1024) {
        float4 v = *reinterpret_cast<const float4*>(&sf[base + t]);
        vals[t] = v.x; vals[t + 1] = v.y; vals[t + 2] = v.z; vals[t + 3] = v.w;
        m = fmaxf(fmaxf(m, fmaxf(v.x, v.y)), fmaxf(v.z, v.w));
    }
    for (int t = len4 + tid; t < len; t += 256) {
        float v = sf[base + t];
        vals[t] = v; m = fmaxf(m, v);
    }
    red[tid] = m; __syncthreads();
    for (int off = 128; off > 0; off >>= 1) {
        if (tid < off) red[tid] = fmaxf(red[tid], red[tid + off]);
        __syncthreads();
    }
    m = red[0]; __syncthreads();

    float sum = 0.f;
    for (int t = tid; t < len; t += 256) {
        float e = __expf(vals[t] - m);
        vals[t] = e; sum += e;
    }
    red[tid] = sum; __syncthreads();
    for (int off = 128; off > 0; off >>= 1) {
        if (tid < off) red[tid] += red[tid + off];
        __syncthreads();
    }
    const float inv = 1.f / red[0];

    const int rowEnd = (s & ~63) + 64;   // out_v GEMM (TM=64) reads k < rowEnd
    for (int t = tid * 8; t < rowEnd; t += 2048) {
        unsigned uh[4], ul[4];
#pragma unroll
        for (int p = 0; p < 4; p++) {
            float a = (t + 2 * p     < len) ? vals[t + 2 * p] * inv : 0.f;
            float b = (t + 2 * p + 1 < len) ? vals[t + 2 * p + 1] * inv : 0.f;
            pack2(a, b, uh[p], ul[p]);
        }
        *reinterpret_cast<uint4*>(&sh[base + t]) = make_uint4(uh[0], uh[1], uh[2], uh[3]);
        *reinterpret_cast<uint4*>(&sl[base + t]) = make_uint4(ul[0], ul[1], ul[2], ul[3]);
    }
}

// =============================================================================
extern "C" void kernel_launch(void* const* d_in, const int* in_sizes, int n_in,
                              void* d_out, int out_size)
{
    const float* hidden = (const float*)d_in[0];
    const float* cosb   = (const float*)d_in[1];
    const float* sinb   = (const float*)d_in[2];
    const float* w_qa   = (const float*)d_in[3];
    const float* qa_ln  = (const float*)d_in[4];
    const float* w_qb   = (const float*)d_in[5];
    const float* w_kva  = (const float*)d_in[6];
    const float* kva_ln = (const float*)d_in[7];
    const float* w_k    = (const float*)d_in[8];
    const float* w_v    = (const float*)d_in[9];
    const float* w_o    = (const float*)d_in[10];
    float* out = (float*)d_out;

    bf16 *hid, *qlat, *q, *lat, *kf, *kcat, *veff, *sc, *ao;
    bf16 *wqa, *wqb, *wkva, *wk, *wvT, *woT;
    float *scf;
    cudaGetSymbolAddress((void**)&hid,  g_hid2);
    cudaGetSymbolAddress((void**)&qlat, g_qlat2);
    cudaGetSymbolAddress((void**)&q,    g_q2);
    cudaGetSymbolAddress((void**)&lat,  g_lat2);
    cudaGetSymbolAddress((void**)&kf,   g_kf2);
    cudaGetSymbolAddress((void**)&kcat, g_kcat2);
    cudaGetSymbolAddress((void**)&veff, g_veff2);
    cudaGetSymbolAddress((void**)&sc,   g_sc2);
    cudaGetSymbolAddress((void**)&scf,  g_scf);
    cudaGetSymbolAddress((void**)&ao,   g_ao2);
    cudaGetSymbolAddress((void**)&wqa,  g_wqa2);
    cudaGetSymbolAddress((void**)&wqb,  g_wqb2);
    cudaGetSymbolAddress((void**)&wkva, g_wkva2);
    cudaGetSymbolAddress((void**)&wk,   g_wk2);
    cudaGetSymbolAddress((void**)&wvT,  g_wv2);
    cudaGetSymbolAddress((void**)&woT,  g_wo2);

    bf16 *hidL = hid + N_HID,  *qlatL = qlat + N_QLAT, *qL = q + N_Q;
    bf16 *latL = lat + N_LAT,  *kfL = kf + N_KF;
    bf16 *kcatL = kcat + N_KCAT, *veffL = veff + N_VEFF;
    bf16 *scL  = sc + N_SC,    *aoL = ao + N_AO;
    bf16 *wqaL = wqa + N_WQA,  *wqbL = wqb + N_WQB,    *wkvaL = wkva + N_WKVA;
    bf16 *wkL  = wk + N_WK,    *wvTL = wvT + N_WV,     *woTL = woT + N_WO;

    constexpr int SM64_4  = 4 * (2 * 64 * 64 + 2 * 128 * 64);   // 98304
    constexpr int SM128_3 = 3 * (2 * 128 * 64 + 2 * 128 * 64);  // 98304
    cudaFuncSetAttribute((void*)mma_gemm<64, 128, 4>,  cudaFuncAttributeMaxDynamicSharedMemorySize, SM64_4);
    cudaFuncSetAttribute((void*)mma_gemm<128, 128, 3>, cudaFuncAttributeMaxDynamicSharedMemorySize, SM128_3);

    const dim3 tb(32, 8);

    // weight prep
    transpose_split<<<dim3(QL_ / 32, HID_ / 32, 1), tb>>>(w_qa, wqa, wqaL, HID_, QL_, QL_, 0, 0);
    transpose_split<<<dim3(NH_ * QDIM_ / 32, QL_ / 32, 1), tb>>>(w_qb, wqb, wqbL, QL_, NH_ * QDIM_, NH_ * QDIM_, 0, 0);
    // split hidden
    {
        long long n = (long long)N_HID;
        split_f32<<<(unsigned)((n + 255) / 256), 256>>>(hidden, hid, hidL, n);
    }
    // launch 3 (profile slot): q_lat = hidden @ w_qa  (TM=64, NSTAGE=4 - control)
    mma_gemm<64, 128, 4><<<dim3(QL_ / 128, S_ / 64, 1), 256, SM64_4>>>(
        hid, hidL, wqa, wqaL, qlat, qlatL, nullptr, nullptr, nullptr,
        S_, QL_, HID_, HID_, HID_, QL_, 0, 0, 0, 1.f, 0);
    rmsnorm_q<<<S_, 256>>>(qlat, qlatL, qa_ln);
    // q = q_lat @ w_qb   (TM=128, NSTAGE=3)
    mma_gemm<128, 128, 3><<<dim3(NH_ * QDIM_ / 128, S_ / 128, 1), 256, SM128_3>>>(
        qlat, qlatL, wqb, wqbL, q, qL, nullptr, nullptr, nullptr,
        S_, NH_ * QDIM_, QL_, QL_, QL_, NH_ * QDIM_, 0, 0, 0, 1.f, 0);
    // rope q_pe in place
    {
        long long tot = (long long)S_ * NH_ * 32;
        rope_q_inplace<<<(unsigned)((tot + 255) / 256), 256>>>(q, qL, cosb, sinb);
    }
    // latent path (TM=64, NSTAGE=4)
    transpose_split<<<dim3(DF_ / 32, HID_ / 32, 1), tb>>>(w_kva, wkva, wkvaL, HID_, DF_, DF_, 0, 0);
    mma_gemm<64, 128, 4><<<dim3((DF_ + 127) / 128, S_ / 64, 1), 256, SM64_4>>>(
        hid, hidL, wkva, wkvaL, lat, latL, nullptr, nullptr, nullptr,
        S_, DF_, HID_, HID_, HID_, DF_, 0, 0, 0, 1.f, 0);
    kva_norm_rope<<<S_, 128>>>(lat, latL, kva_ln, cosb, sinb, kf, kfL);

    // ---- K_eff + fused pe broadcast: kcat[h][t][:]  (TM=128) ----
    {
        long long n = (long long)N_WK;
        split_f32<<<(unsigned)((n + 255) / 256), 256>>>(w_k, wk, wkL, n);
    }
    mma_gemm<128, 128, 3><<<dim3(1, S_ / 128, NH_), 256, SM128_3>>>(
        kf, kfL, wk, wkL, kcat, kcatL, nullptr, kf, kfL,
        S_, DN_, KVL_, DF_, KVL_, KCAT_,
        0LL, (long long)DN_ * KVL_, (long long)S_ * KCAT_, 1.f, 8);
    // ---- V_eff^T[h] = w_v[h]^T @ c_kv^T  (TM=64; M=128) ----
    transpose_split<<<dim3(DV_ / 32, KVL_ / 32, NH_), tb>>>(w_v, wvT, wvTL, KVL_, DV_, DV_,
        (long long)KVL_ * DV_, (long long)DV_ * KVL_);
    mma_gemm<64, 128, 4><<<dim3(S_ / 128, DV_ / 64, NH_), 256, SM64_4>>>(
        wvT, wvTL, kf, kfL, veff, veffL, nullptr, nullptr, nullptr,
        DV_, S_, KVL_, KVL_, DF_, S_,
        (long long)DV_ * KVL_, 0LL, (long long)DV_ * S_, 1.f, 0);

    // ---- scores = SM_SCALE * q[h] @ kcat[h]^T  (K=192, causal skip, TM=128) --
    mma_gemm<128, 128, 3><<<dim3(S_ / 128, S_ / 128, NH_), 256, SM128_3>>>(
        q, qL, kcat, kcatL, nullptr, nullptr, scf, nullptr, nullptr,
        S_, S_, KCAT_, NH_ * QDIM_, KCAT_, S_,
        (long long)QDIM_, (long long)S_ * KCAT_, (long long)S_ * S_, SM_SCALE_, 1 | 4);
    // softmax (rowEnd 64-block, matches out_v TM=64)
    softmax_causal<<<dim3(S_, NH_), 256>>>(scf, sc, scL);
    // ---- ao[:, h*128:+128] = attn[h] @ V_eff[h]  (TM=64, K-limit row0+64) ----
    mma_gemm<64, 128, 4><<<dim3(1, S_ / 64, NH_), 256, SM64_4>>>(
        sc, scL, veff, veffL, ao, aoL, nullptr, nullptr, nullptr,
        S_, DV_, S_, S_, S_, NH_ * DV_,
        (long long)S_ * S_, (long long)DV_ * S_, (long long)DV_, 1.f, 2);
    // out = ao @ w_o  (TM=128, NSTAGE=3)
    transpose_split<<<dim3(HID_ / 32, (NH_ * DV_) / 32, 1), tb>>>(w_o, woT, woTL, NH_ * DV_, HID_, HID_, 0, 0);
    mma_gemm<128, 128, 3><<<dim3(HID_ / 128, S_ / 128, 1), 256, SM128_3>>>(
        ao, aoL, woT, woTL, nullptr, nullptr, out, nullptr, nullptr,
        S_, HID_, NH_ * DV_, NH_ * DV_, NH_ * DV_, HID_, 0, 0, 0, 1.f, 4);
}